// round 2
// baseline (speedup 1.0000x reference)
#include <cuda_runtime.h>
#include <cuda_bf16.h>
#include <math.h>

// ---------------- problem constants ----------------
#define BB 4
#define CCH 64
#define CSV 16
#define NN 2048
#define TT0 64
#define TT1 62
#define TT2 60
#define TT3 58
#define TT4 56
#define EE 32768
#define MM (BB*TT2)   // 240
#define TOT4 (BB*CCH*NN*TT4)  // 29360128
#define EPSBN 1e-5f

// ---------------- scratch (device globals; no runtime alloc) ----------------
__device__ float g_bufA[(size_t)BB*CCH*NN*TT1];   // conv1 out / conv3 out
__device__ float g_bufB[(size_t)BB*CCH*NN*TT2];   // conv2 out / conv4 out
__device__ float g_bufS[(size_t)TOT4];            // relu(bn2)+residual
__device__ float g_A0[(size_t)NN*MM*CSV];
__device__ float g_Y1[(size_t)NN*MM*CSV];
__device__ float g_Y2[(size_t)NN*MM*CSV];
__device__ float g_U [(size_t)NN*MM*CSV];
__device__ float g_CH[(size_t)BB*CSV*NN*TT2];     // cheb out in (b,c,n,t)
__device__ float g_degw[NN];
__device__ int   g_cnt[NN];
__device__ int   g_off[NN];
__device__ int   g_rowptr[NN+1];
__device__ int   g_ccol[EE];
__device__ float g_cw[EE];
__device__ double g_part[64*32*2];
__device__ float g_stats[6*64];   // [0]mu1 [64]rs1 [128]mu2 [192]rs2 [256]muf [320]rsf

// ---------------- small graph-prep kernels ----------------
__global__ void zero_k() {
    int i = blockIdx.x*blockDim.x + threadIdx.x;
    if (i < NN) { g_degw[i]=0.f; g_cnt[i]=0; g_off[i]=0; }
}
__global__ void deg_k(const int* __restrict__ ei, const float* __restrict__ ew) {
    int e = blockIdx.x*blockDim.x + threadIdx.x;
    if (e < EE) {
        int r = ei[e];
        atomicAdd(&g_degw[r], ew[e]);
        atomicAdd(&g_cnt[r], 1);
    }
}
__global__ void scan_k() {
    __shared__ int a[NN], btmp[NN];
    int tid = threadIdx.x;               // 1024 threads
    a[tid] = g_cnt[tid]; a[tid+1024] = g_cnt[tid+1024];
    __syncthreads();
    int* src = a; int* dst = btmp;
    for (int off = 1; off < NN; off <<= 1) {
        for (int i = tid; i < NN; i += 1024) {
            int v = src[i];
            if (i >= off) v += src[i-off];
            dst[i] = v;
        }
        __syncthreads();
        int* t = src; src = dst; dst = t;
    }
    if (tid == 0) g_rowptr[0] = 0;
    for (int i = tid; i < NN; i += 1024) g_rowptr[i+1] = src[i];
}
__global__ void fill_k(const int* __restrict__ ei, const float* __restrict__ ew) {
    int e = blockIdx.x*blockDim.x + threadIdx.x;
    if (e < EE) {
        int r = ei[e], c = ei[EE+e];
        float dr = g_degw[r], dc = g_degw[c];
        float ir = dr > 0.f ? rsqrtf(dr) : 0.f;
        float ic = dc > 0.f ? rsqrtf(dc) : 0.f;
        float nrm = -ir * ew[e] * ic;
        int pos = g_rowptr[r] + atomicAdd(&g_off[r], 1);
        g_ccol[pos] = c;
        g_cw[pos]   = nrm;
    }
}

// ---------------- temporal conv (1xKS VALID), 64 out channels ----------------
// block: (16 t-groups of 4) x (OCT/4 o-groups of 4); one (b,n) per block (z = o tile)
template<int CIN, int TIN, int TOUT, int OCT, bool RELU>
__global__ void conv_k(const float* __restrict__ src, const float* __restrict__ w,
                       const float* __restrict__ bias, float* __restrict__ dst) {
    constexpr int XSZ = (CIN*TIN > OCT*TOUT) ? CIN*TIN : OCT*TOUT;
    __shared__ float xs[XSZ];
    __shared__ float ws[CIN*3*OCT];
    const int n = blockIdx.x, b = blockIdx.y, o0 = blockIdx.z*OCT;
    const int nth = 16*(OCT/4);
    const int tid = threadIdx.y*16 + threadIdx.x;

    for (int idx = tid; idx < CIN*TIN; idx += nth) {
        int i = idx / TIN, t = idx - i*TIN;
        xs[idx] = src[(((size_t)b*CIN + i)*NN + n)*TIN + t];
    }
    for (int idx = tid; idx < CIN*3*OCT; idx += nth) {
        int k = idx / OCT, ol = idx - k*OCT;
        int i = k/3, kt = k - i*3;
        ws[idx] = w[((o0+ol)*CIN + i)*3 + kt];
    }
    __syncthreads();

    const int t0 = threadIdx.x*4;
    const int ob = threadIdx.y*4;
    float acc[4][4];
    #pragma unroll
    for (int j = 0; j < 4; j++) {
        #pragma unroll
        for (int u = 0; u < 4; u++) acc[j][u] = 0.f;
    }

    #pragma unroll 4
    for (int i = 0; i < CIN; i++) {
        float xv[6];
        #pragma unroll
        for (int u = 0; u < 6; u++) {
            int t = t0 + u;
            xv[u] = (t < TIN) ? xs[i*TIN + t] : 0.f;
        }
        #pragma unroll
        for (int kt = 0; kt < 3; kt++) {
            #pragma unroll
            for (int j = 0; j < 4; j++) {
                float wv = ws[(i*3+kt)*OCT + ob + j];
                #pragma unroll
                for (int u = 0; u < 4; u++)
                    acc[j][u] = fmaf(wv, xv[u+kt], acc[j][u]);
            }
        }
    }
    __syncthreads();  // done reading xs; reuse as output stage
    #pragma unroll
    for (int j = 0; j < 4; j++) {
        float bo = bias[o0 + ob + j];
        #pragma unroll
        for (int u = 0; u < 4; u++) {
            int t = t0 + u;
            if (t < TOUT) {
                float v = acc[j][u] + bo;
                if (RELU) v = fmaxf(v, 0.f);
                xs[(ob+j)*TOUT + t] = v;
            }
        }
    }
    __syncthreads();
    for (int idx = tid; idx < OCT*TOUT; idx += nth) {
        int o = idx / TOUT, t = idx - o*TOUT;
        dst[(((size_t)b*CCH + o0 + o)*NN + n)*TOUT + t] = xs[idx];
    }
}

// ---------------- BN stats (deterministic, double accumulation) -------------
template<int T>
__global__ void stats_k(const float* __restrict__ src) {
    int c = blockIdx.x, s = blockIdx.y, tid = threadIdx.x;
    double sum = 0.0, sq = 0.0;
    for (int b = 0; b < BB; b++) {
        const float* p = src + (((size_t)b*CCH + c)*NN + s*64)*T;
        for (int i = tid; i < 64*T; i += 256) {
            float v = p[i];
            sum += v;
            sq  += (double)v * v;
        }
    }
    __shared__ double sh[512];
    sh[tid] = sum; sh[tid+256] = sq;
    __syncthreads();
    for (int st = 128; st > 0; st >>= 1) {
        if (tid < st) { sh[tid] += sh[tid+st]; sh[tid+256] += sh[tid+256+st]; }
        __syncthreads();
    }
    if (tid == 0) {
        g_part[(c*32+s)*2]   = sh[0];
        g_part[(c*32+s)*2+1] = sh[256];
    }
}
__global__ void bnfin_k(int base, double inv_cnt) {
    int c = threadIdx.x;   // 64 threads
    double s = 0.0, q = 0.0;
    for (int i = 0; i < 32; i++) { s += g_part[(c*32+i)*2]; q += g_part[(c*32+i)*2+1]; }
    double mu = s * inv_cnt;
    double var = q * inv_cnt - mu*mu;
    g_stats[base + c]      = (float)mu;
    g_stats[base + 64 + c] = (float)(1.0 / sqrt(var + (double)EPSBN));
}

// ---------------- Cheb channel-mix GEMM (fused bn1+relu input) --------------
// out j<16: Tx0(W0-W2) -> g_A0 ; 16..31: Tx0 W1 -> g_Y1 ; 32..47: Tx0 W2 -> g_Y2
__global__ void chebgemm_k(const float* __restrict__ src, const float* __restrict__ g1,
                           const float* __restrict__ b1, const float* __restrict__ chebW) {
    __shared__ float xs[64*TT2];
    __shared__ float ws[64*48];
    __shared__ float stg[TT2*48];
    __shared__ float bna[64], bnb[64];
    const int n = blockIdx.x, b = blockIdx.y, tid = threadIdx.x;  // 120 threads
    if (tid < 64) {
        float mu = g_stats[tid], rs = g_stats[64+tid];
        float a = g1[tid]*rs;
        bna[tid] = a; bnb[tid] = b1[tid] - a*mu;
    }
    __syncthreads();
    for (int idx = tid; idx < 64*TT2; idx += 120) {
        int c = idx / TT2, t = idx - c*TT2;
        float y = src[(((size_t)b*CCH + c)*NN + n)*TT2 + t];
        xs[idx] = fmaxf(bna[c]*y + bnb[c], 0.f);
    }
    for (int idx = tid; idx < 64*48; idx += 120) {
        int c = idx / 48, j = idx - c*48;
        int jj = j & 15;
        float v;
        if (j < 16)      v = chebW[c*16 + jj] - chebW[(128+c)*16 + jj];
        else if (j < 32) v = chebW[(64+c)*16 + jj];
        else             v = chebW[(128+c)*16 + jj];
        ws[idx] = v;
    }
    __syncthreads();
    const int jp = tid % 24, tg = tid / 24;
    const int j0 = jp*2, t0 = tg*12;
    float a0[12], a1[12];
    #pragma unroll
    for (int u = 0; u < 12; u++) { a0[u] = 0.f; a1[u] = 0.f; }
    #pragma unroll 4
    for (int c = 0; c < 64; c++) {
        float w0 = ws[c*48 + j0], w1 = ws[c*48 + j0 + 1];
        #pragma unroll
        for (int u = 0; u < 12; u++) {
            float xv = xs[c*TT2 + t0 + u];
            a0[u] = fmaf(w0, xv, a0[u]);
            a1[u] = fmaf(w1, xv, a1[u]);
        }
    }
    #pragma unroll
    for (int u = 0; u < 12; u++) {
        stg[(t0+u)*48 + j0]     = a0[u];
        stg[(t0+u)*48 + j0 + 1] = a1[u];
    }
    __syncthreads();
    for (int idx = tid; idx < TT2*48; idx += 120) {
        int t = idx / 48, j = idx - t*48;
        int part = j >> 4, cc = j & 15;
        float* d = (part == 0) ? g_A0 : ((part == 1) ? g_Y1 : g_Y2);
        d[(size_t)n*MM*CSV + (b*TT2 + t)*CSV + cc] = stg[idx];
    }
}

// ---------------- sparse propagation (CSR gather, 16 channels) --------------
__global__ void prop1_k() {   // U = Y1 + 2*prop(Y2)
    const int n = blockIdx.x, tid = threadIdx.x;  // 256 threads
    const int s = g_rowptr[n], e = g_rowptr[n+1];
    float acc[15];
    #pragma unroll
    for (int k = 0; k < 15; k++) acc[k] = 0.f;
    for (int i = s; i < e; i++) {
        int col = g_ccol[i]; float w = g_cw[i];
        const float* zp = g_Y2 + (size_t)col*(MM*CSV) + tid;
        #pragma unroll
        for (int k = 0; k < 15; k++) acc[k] = fmaf(w, zp[k*256], acc[k]);
    }
    size_t base = (size_t)n*(MM*CSV) + tid;
    #pragma unroll
    for (int k = 0; k < 15; k++) g_U[base + k*256] = g_Y1[base + k*256] + 2.f*acc[k];
}
__global__ void prop2_k(const float* __restrict__ chebB) {  // relu(A0+prop(U)+b) -> CH
    const int n = blockIdx.x, tid = threadIdx.x;
    const int s = g_rowptr[n], e = g_rowptr[n+1];
    float acc[15];
    #pragma unroll
    for (int k = 0; k < 15; k++) acc[k] = 0.f;
    for (int i = s; i < e; i++) {
        int col = g_ccol[i]; float w = g_cw[i];
        const float* zp = g_U + (size_t)col*(MM*CSV) + tid;
        #pragma unroll
        for (int k = 0; k < 15; k++) acc[k] = fmaf(w, zp[k*256], acc[k]);
    }
    __shared__ float sv[MM*CSV];
    size_t base = (size_t)n*(MM*CSV);
    #pragma unroll
    for (int k = 0; k < 15; k++) {
        int f = tid + k*256;
        int c = f & 15;
        float v = g_A0[base + f] + acc[k] + chebB[c];
        sv[f] = fmaxf(v, 0.f);
    }
    __syncthreads();
    for (int idx = tid; idx < MM*CSV; idx += 256) {
        int bc = idx / TT2, t = idx - bc*TT2;
        int b = bc >> 4, cc = bc & 15;
        g_CH[(((size_t)b*CSV + cc)*NN + n)*TT2 + t] = sv[(b*TT2 + t)*CSV + cc];
    }
}

// ---------------- tail: bn2+relu+residual, bnf+relu ----------------
__global__ void addres_k(const float* __restrict__ y, const float* __restrict__ x,
                         const float* __restrict__ g2, const float* __restrict__ b2) {
    int idx = blockIdx.x*256 + threadIdx.x;
    if (idx >= TOT4) return;
    int t = idx % TT4;
    int r = idx / TT4;
    int n = r % NN;
    int bc = r / NN;
    int c = bc & 63;
    float mu = g_stats[128+c], rs = g_stats[192+c];
    float a = g2[c]*rs;
    float bb = b2[c] - a*mu;
    float h = fmaxf(a*y[idx] + bb, 0.f);
    g_bufS[idx] = h + x[((size_t)bc*NN + n)*TT0 + t];
}
__global__ void final_k(const float* __restrict__ gf, const float* __restrict__ bf,
                        float* __restrict__ out) {
    int idx = blockIdx.x*256 + threadIdx.x;
    if (idx >= TOT4) return;
    int c = (idx / (TT4*NN)) & 63;
    float mu = g_stats[256+c], rs = g_stats[320+c];
    float a = gf[c]*rs;
    float bb = bf[c] - a*mu;
    out[idx] = fmaxf(a*g_bufS[idx] + bb, 0.f);
}

// ---------------- host ----------------
static float* symf(const void* p) { return (float*)p; }

extern "C" void kernel_launch(void* const* d_in, const int* in_sizes, int n_in,
                              void* d_out, int out_size) {
    const float* x    = (const float*)d_in[0];
    const int*   ei   = (const int*)  d_in[1];
    const float* ew   = (const float*)d_in[2];
    const float* t1w1 = (const float*)d_in[3];
    const float* t1b1 = (const float*)d_in[4];
    const float* t1w2 = (const float*)d_in[5];
    const float* t1b2 = (const float*)d_in[6];
    const float* bn1g = (const float*)d_in[7];
    const float* bn1b = (const float*)d_in[8];
    const float* chebW= (const float*)d_in[9];
    const float* chebB= (const float*)d_in[10];
    const float* t2w1 = (const float*)d_in[11];
    const float* t2b1 = (const float*)d_in[12];
    const float* t2w2 = (const float*)d_in[13];
    const float* t2b2 = (const float*)d_in[14];
    const float* bn2g = (const float*)d_in[15];
    const float* bn2b = (const float*)d_in[16];
    const float* bnfg = (const float*)d_in[17];
    const float* bnfb = (const float*)d_in[18];
    float* out = (float*)d_out;

    void *pA, *pB, *pS, *pCH;
    cudaGetSymbolAddress(&pA, g_bufA);
    cudaGetSymbolAddress(&pB, g_bufB);
    cudaGetSymbolAddress(&pS, g_bufS);
    cudaGetSymbolAddress(&pCH, g_CH);
    float* bufA = symf(pA);
    float* bufB = symf(pB);
    float* bufS = symf(pS);
    float* CH   = symf(pCH);

    // graph prep: deg -> rowptr -> CSR fill (norm)
    zero_k<<<(NN+255)/256, 256>>>();
    deg_k<<<EE/256, 256>>>(ei, ew);
    scan_k<<<1, 1024>>>();
    fill_k<<<EE/256, 256>>>(ei, ew);

    // conv1 (relu) : x -> bufA
    conv_k<CCH, TT0, TT1, 32, true><<<dim3(NN, BB, 2), dim3(16, 8)>>>(x, t1w1, t1b1, bufA);
    // conv2 (raw)  : bufA -> bufB, then bn1 stats
    conv_k<CCH, TT1, TT2, 32, false><<<dim3(NN, BB, 2), dim3(16, 8)>>>(bufA, t1w2, t1b2, bufB);
    stats_k<TT2><<<dim3(64, 32), 256>>>(bufB);
    bnfin_k<<<1, 64>>>(0, 1.0 / (double)(BB*NN*TT2));

    // cheb: projected-first formulation
    chebgemm_k<<<dim3(NN, BB), 120>>>(bufB, bn1g, bn1b, chebW);
    prop1_k<<<NN, 256>>>();
    prop2_k<<<NN, 256>>>(chebB);

    // conv3 (relu) : CH -> bufA ; conv4 (raw) : bufA -> bufB, then bn2 stats
    conv_k<CSV, TT2, TT3, 64, true><<<dim3(NN, BB, 1), dim3(16, 16)>>>(CH, t2w1, t2b1, bufA);
    conv_k<CCH, TT3, TT4, 32, false><<<dim3(NN, BB, 2), dim3(16, 8)>>>(bufA, t2w2, t2b2, bufB);
    stats_k<TT4><<<dim3(64, 32), 256>>>(bufB);
    bnfin_k<<<1, 64>>>(128, 1.0 / (double)(BB*NN*TT4));

    // s = relu(bn2(conv4)) + residual ; bnf stats ; final
    addres_k<<<(TOT4+255)/256, 256>>>(bufB, x, bn2g, bn2b);
    stats_k<TT4><<<dim3(64, 32), 256>>>(bufS);
    bnfin_k<<<1, 64>>>(256, 1.0 / (double)(BB*NN*TT4));
    final_k<<<(TOT4+255)/256, 256>>>(bnfg, bnfb, out);
}

// round 5
// speedup vs baseline: 1.2593x; 1.2593x over previous
#include <cuda_runtime.h>
#include <cuda_bf16.h>
#include <math.h>

// ---------------- problem constants ----------------
#define BB 4
#define CCH 64
#define CSV 16
#define NN 2048
#define TT0 64
#define TT1 62
#define TT2 60
#define TT3 58
#define TT4 56
#define EE 32768
#define MM (BB*TT2)   // 240
#define FDIM (MM*CSV) // 3840
#define TOT4 (BB*CCH*NN*TT4)  // 29360128
#define EPSBN 1e-5f
#define TINP 68       // padded smem row (zero-filled tail), mult of 4

typedef unsigned long long u64;

// ---------------- f32x2 packed helpers ----------------
__device__ __forceinline__ u64 pk(float lo, float hi) {
    u64 r; asm("mov.b64 %0, {%1, %2};" : "=l"(r) : "f"(lo), "f"(hi)); return r;
}
__device__ __forceinline__ void unpk(u64 v, float& lo, float& hi) {
    asm("mov.b64 {%0, %1}, %2;" : "=f"(lo), "=f"(hi) : "l"(v));
}
__device__ __forceinline__ void ffma2(u64& d, u64 a, u64 b) {
    asm("fma.rn.f32x2 %0, %1, %2, %0;" : "+l"(d) : "l"(a), "l"(b));
}

// ---------------- scratch (device globals; no runtime alloc) ----------------
__device__ float g_bufA[(size_t)BB*CCH*NN*TT1];   // conv1 out / conv3 out
__device__ float g_bufB[(size_t)BB*CCH*NN*TT2];   // conv2 out / conv4 out
__device__ float g_bufS[(size_t)TOT4];            // relu(bn2)+residual
__device__ float g_A0[(size_t)NN*FDIM];
__device__ float g_Y1[(size_t)NN*FDIM];
__device__ float g_Y2[(size_t)NN*FDIM];
__device__ float g_U [(size_t)NN*FDIM];
__device__ float g_CH[(size_t)BB*CSV*NN*TT2];     // cheb out in (b,c,n,t)
__device__ float g_degw[NN];
__device__ int   g_cnt[NN];
__device__ int   g_off[NN];
__device__ int   g_rowptr[NN+1];
__device__ int   g_ccol[EE];
__device__ float g_cw[EE];
__device__ float g_part[64*32*2];
__device__ float g_stats[6*64];   // [0]mu1 [64]rs1 [128]mu2 [192]rs2 [256]muf [320]rsf

// ---------------- small graph-prep kernels ----------------
__global__ void zero_k() {
    int i = blockIdx.x*blockDim.x + threadIdx.x;
    if (i < NN) { g_degw[i]=0.f; g_cnt[i]=0; g_off[i]=0; }
}
__global__ void deg_k(const int* __restrict__ ei, const float* __restrict__ ew) {
    int e = blockIdx.x*blockDim.x + threadIdx.x;
    if (e < EE) {
        int r = ei[e];
        atomicAdd(&g_degw[r], ew[e]);
        atomicAdd(&g_cnt[r], 1);
    }
}
__global__ void scan_k() {
    __shared__ int a[NN], btmp[NN];
    int tid = threadIdx.x;               // 1024 threads
    a[tid] = g_cnt[tid]; a[tid+1024] = g_cnt[tid+1024];
    __syncthreads();
    int* src = a; int* dst = btmp;
    for (int off = 1; off < NN; off <<= 1) {
        for (int i = tid; i < NN; i += 1024) {
            int v = src[i];
            if (i >= off) v += src[i-off];
            dst[i] = v;
        }
        __syncthreads();
        int* t = src; src = dst; dst = t;
    }
    if (tid == 0) g_rowptr[0] = 0;
    for (int i = tid; i < NN; i += 1024) g_rowptr[i+1] = src[i];
}
__global__ void fill_k(const int* __restrict__ ei, const float* __restrict__ ew) {
    int e = blockIdx.x*blockDim.x + threadIdx.x;
    if (e < EE) {
        int r = ei[e], c = ei[EE+e];
        float dr = g_degw[r], dc = g_degw[c];
        float ir = dr > 0.f ? rsqrtf(dr) : 0.f;
        float ic = dc > 0.f ? rsqrtf(dc) : 0.f;
        float nrm = -ir * ew[e] * ic;
        int pos = g_rowptr[r] + atomicAdd(&g_off[r], 1);
        g_ccol[pos] = c;
        g_cw[pos]   = nrm;
    }
}

// ---------------- temporal conv (1xKS VALID), FFMA2 inner loop --------------
// block: 16 t-threads x (OCT/4) o-threads; one (b,n) per block (z = o tile).
// Thread computes 4 o (2 f32x2 pairs along o) x 4 t.
template<int CIN, int TIN, int TOUT, int OCT, bool RELU>
__global__ void conv_k(const float* __restrict__ src, const float* __restrict__ w,
                       const float* __restrict__ bias, float* __restrict__ dst) {
    constexpr int XSZ = (CIN*TINP > OCT*TOUT) ? CIN*TINP : OCT*TOUT;
    constexpr int NTH = 16*(OCT/4);
    __shared__ float xs[XSZ];
    __shared__ float ws[CIN*3*OCT];
    const int n = blockIdx.x, b = blockIdx.y, o0 = blockIdx.z*OCT;
    const int tid = threadIdx.y*16 + threadIdx.x;

    for (int idx = tid; idx < CIN*TINP; idx += NTH) {
        int i = idx / TINP, t = idx - i*TINP;
        xs[idx] = (t < TIN) ? src[(((size_t)b*CIN + i)*NN + n)*TIN + t] : 0.f;
    }
    for (int idx = tid; idx < CIN*3*OCT; idx += NTH) {
        int k = idx / OCT, ol = idx - k*OCT;
        int i = k/3, kt = k - i*3;
        ws[idx] = w[((o0+ol)*CIN + i)*3 + kt];
    }
    __syncthreads();

    const int t0 = threadIdx.x*4;
    const int ob = threadIdx.y*4;
    u64 acc[2][4];
    #pragma unroll
    for (int jp = 0; jp < 2; jp++) {
        #pragma unroll
        for (int u = 0; u < 4; u++) acc[jp][u] = 0ull;
    }

    #pragma unroll 2
    for (int i = 0; i < CIN; i++) {
        const float4 xa = *reinterpret_cast<const float4*>(&xs[i*TINP + t0]);
        const float2 xb = *reinterpret_cast<const float2*>(&xs[i*TINP + t0 + 4]);
        u64 xd[6];
        xd[0] = pk(xa.x, xa.x); xd[1] = pk(xa.y, xa.y); xd[2] = pk(xa.z, xa.z);
        xd[3] = pk(xa.w, xa.w); xd[4] = pk(xb.x, xb.x); xd[5] = pk(xb.y, xb.y);
        #pragma unroll
        for (int kt = 0; kt < 3; kt++) {
            ulonglong2 wq = *reinterpret_cast<const ulonglong2*>(&ws[(i*3+kt)*OCT + ob]);
            #pragma unroll
            for (int u = 0; u < 4; u++) {
                ffma2(acc[0][u], wq.x, xd[kt+u]);   // outputs (ob, ob+1)
                ffma2(acc[1][u], wq.y, xd[kt+u]);   // outputs (ob+2, ob+3)
            }
        }
    }
    __syncthreads();  // done reading xs; reuse as output stage

    float b01_lo = bias[o0+ob+0], b01_hi = bias[o0+ob+1];
    float b23_lo = bias[o0+ob+2], b23_hi = bias[o0+ob+3];
    #pragma unroll
    for (int jp = 0; jp < 2; jp++) {
        float blo = (jp == 0) ? b01_lo : b23_lo;
        float bhi = (jp == 0) ? b01_hi : b23_hi;
        int olo = ob + jp*2, ohi = olo + 1;
        #pragma unroll
        for (int u = 0; u < 4; u++) {
            int t = t0 + u;
            if (t < TOUT) {
                float lo, hi; unpk(acc[jp][u], lo, hi);
                float v0 = lo + blo, v1 = hi + bhi;
                if (RELU) { v0 = fmaxf(v0, 0.f); v1 = fmaxf(v1, 0.f); }
                xs[olo*TOUT + t] = v0;
                xs[ohi*TOUT + t] = v1;
            }
        }
    }
    __syncthreads();
    for (int idx = tid; idx < OCT*TOUT; idx += NTH) {
        int o = idx / TOUT, t = idx - o*TOUT;
        dst[(((size_t)b*CCH + o0 + o)*NN + n)*TOUT + t] = xs[idx];
    }
}

// ---------------- BN stats (fp32, float4 loads, deterministic) --------------
template<int T>
__global__ void stats_k(const float* __restrict__ src) {
    int c = blockIdx.x, s = blockIdx.y, tid = threadIdx.x;  // 256 thr
    float sum = 0.f, sq = 0.f;
    for (int b = 0; b < BB; b++) {
        const float4* p = reinterpret_cast<const float4*>(src + (((size_t)b*CCH + c)*NN + s*64)*T);
        const int n4 = 64*T/4;
        for (int i = tid; i < n4; i += 256) {
            float4 v = p[i];
            sum += (v.x + v.y) + (v.z + v.w);
            sq  += (v.x*v.x + v.y*v.y) + (v.z*v.z + v.w*v.w);
        }
    }
    __shared__ float sh[512];
    sh[tid] = sum; sh[tid+256] = sq;
    __syncthreads();
    for (int st = 128; st > 0; st >>= 1) {
        if (tid < st) { sh[tid] += sh[tid+st]; sh[tid+256] += sh[tid+256+st]; }
        __syncthreads();
    }
    if (tid == 0) {
        g_part[(c*32+s)*2]   = sh[0];
        g_part[(c*32+s)*2+1] = sh[256];
    }
}
__global__ void bnfin_k(int base, float inv_cnt) {
    int c = threadIdx.x;   // 64 threads
    float s = 0.f, q = 0.f;
    for (int i = 0; i < 32; i++) { s += g_part[(c*32+i)*2]; q += g_part[(c*32+i)*2+1]; }
    float mu = s * inv_cnt;
    float var = q * inv_cnt - mu*mu;
    g_stats[base + c]      = mu;
    g_stats[base + 64 + c] = (float)(1.0 / sqrt((double)var + (double)EPSBN));
}

// ---------------- Cheb channel-mix GEMM (fused bn1+relu input, FFMA2) -------
// out j<16: Tx0(W0-W2) -> g_A0 ; 16..31: Tx0 W1 -> g_Y1 ; 32..47: Tx0 W2 -> g_Y2
__global__ void chebgemm_k(const float* __restrict__ src, const float* __restrict__ g1,
                           const float* __restrict__ b1, const float* __restrict__ chebW) {
    __shared__ float xs[64*TT2];
    __shared__ float ws[64*48];
    __shared__ float stg[TT2*48];
    __shared__ float bna[64], bnb[64];
    const int n = blockIdx.x, b = blockIdx.y, tid = threadIdx.x;  // 120 threads
    if (tid < 64) {
        float mu = g_stats[tid], rs = g_stats[64+tid];
        float a = g1[tid]*rs;
        bna[tid] = a; bnb[tid] = b1[tid] - a*mu;
    }
    __syncthreads();
    for (int idx = tid; idx < 64*TT2; idx += 120) {
        int c = idx / TT2, t = idx - c*TT2;
        float y = src[(((size_t)b*CCH + c)*NN + n)*TT2 + t];
        xs[idx] = fmaxf(bna[c]*y + bnb[c], 0.f);
    }
    for (int idx = tid; idx < 64*48; idx += 120) {
        int c = idx / 48, j = idx - c*48;
        int jj = j & 15;
        float v;
        if (j < 16)      v = chebW[c*16 + jj] - chebW[(128+c)*16 + jj];
        else if (j < 32) v = chebW[(64+c)*16 + jj];
        else             v = chebW[(128+c)*16 + jj];
        ws[idx] = v;
    }
    __syncthreads();
    const int jp = tid % 24, tg = tid / 24;
    const int j0 = jp*2, t0 = tg*12;
    u64 p0[6], p1[6];
    #pragma unroll
    for (int u = 0; u < 6; u++) { p0[u] = 0ull; p1[u] = 0ull; }
    #pragma unroll 2
    for (int c = 0; c < 64; c++) {
        const float4 xa = *reinterpret_cast<const float4*>(&xs[c*TT2 + t0]);
        const float4 xb = *reinterpret_cast<const float4*>(&xs[c*TT2 + t0 + 4]);
        const float4 xc = *reinterpret_cast<const float4*>(&xs[c*TT2 + t0 + 8]);
        u64 xp[6];
        xp[0] = pk(xa.x, xa.y); xp[1] = pk(xa.z, xa.w);
        xp[2] = pk(xb.x, xb.y); xp[3] = pk(xb.z, xb.w);
        xp[4] = pk(xc.x, xc.y); xp[5] = pk(xc.z, xc.w);
        float w0 = ws[c*48 + j0], w1 = ws[c*48 + j0 + 1];
        u64 w0d = pk(w0, w0), w1d = pk(w1, w1);
        #pragma unroll
        for (int u = 0; u < 6; u++) {
            ffma2(p0[u], w0d, xp[u]);
            ffma2(p1[u], w1d, xp[u]);
        }
    }
    #pragma unroll
    for (int u = 0; u < 6; u++) {
        float lo, hi;
        unpk(p0[u], lo, hi);
        stg[(t0+2*u)*48 + j0]       = lo;
        stg[(t0+2*u+1)*48 + j0]     = hi;
        unpk(p1[u], lo, hi);
        stg[(t0+2*u)*48 + j0 + 1]   = lo;
        stg[(t0+2*u+1)*48 + j0 + 1] = hi;
    }
    __syncthreads();
    for (int idx = tid; idx < TT2*48; idx += 120) {
        int t = idx / 48, j = idx - t*48;
        int part = j >> 4, cc = j & 15;
        float* d = (part == 0) ? g_A0 : ((part == 1) ? g_Y1 : g_Y2);
        d[(size_t)n*FDIM + (b*TT2 + t)*CSV + cc] = stg[idx];
    }
}

// ---------------- sparse propagation (CSR gather, float4) -------------------
// 240 threads: thread handles 16 consecutive features (4 float4).
__global__ void prop1_k() {   // U = Y1 + 2*prop(Y2)
    const int n = blockIdx.x, tid = threadIdx.x;  // 240 threads
    const int s = g_rowptr[n], e = g_rowptr[n+1];
    float4 acc[4];
    #pragma unroll
    for (int k = 0; k < 4; k++) acc[k] = make_float4(0.f,0.f,0.f,0.f);
    for (int i = s; i < e; i++) {
        int col = g_ccol[i]; float w = g_cw[i];
        const float4* zp = reinterpret_cast<const float4*>(g_Y2 + (size_t)col*FDIM) + tid*4;
        #pragma unroll
        for (int k = 0; k < 4; k++) {
            float4 v = zp[k];
            acc[k].x = fmaf(w, v.x, acc[k].x);
            acc[k].y = fmaf(w, v.y, acc[k].y);
            acc[k].z = fmaf(w, v.z, acc[k].z);
            acc[k].w = fmaf(w, v.w, acc[k].w);
        }
    }
    const float4* y1 = reinterpret_cast<const float4*>(g_Y1 + (size_t)n*FDIM) + tid*4;
    float4* up = reinterpret_cast<float4*>(g_U + (size_t)n*FDIM) + tid*4;
    #pragma unroll
    for (int k = 0; k < 4; k++) {
        float4 a = y1[k];
        a.x += 2.f*acc[k].x; a.y += 2.f*acc[k].y;
        a.z += 2.f*acc[k].z; a.w += 2.f*acc[k].w;
        up[k] = a;
    }
}
__global__ void prop2_k(const float* __restrict__ chebB) {  // relu(A0+prop(U)+b) -> CH
    const int n = blockIdx.x, tid = threadIdx.x;   // 256 threads (240 accumulate)
    const int s = g_rowptr[n], e = g_rowptr[n+1];
    __shared__ float sv[FDIM];
    if (tid < 240) {
        float4 acc[4];
        #pragma unroll
        for (int k = 0; k < 4; k++) acc[k] = make_float4(0.f,0.f,0.f,0.f);
        for (int i = s; i < e; i++) {
            int col = g_ccol[i]; float w = g_cw[i];
            const float4* zp = reinterpret_cast<const float4*>(g_U + (size_t)col*FDIM) + tid*4;
            #pragma unroll
            for (int k = 0; k < 4; k++) {
                float4 v = zp[k];
                acc[k].x = fmaf(w, v.x, acc[k].x);
                acc[k].y = fmaf(w, v.y, acc[k].y);
                acc[k].z = fmaf(w, v.z, acc[k].z);
                acc[k].w = fmaf(w, v.w, acc[k].w);
            }
        }
        const float4* a0 = reinterpret_cast<const float4*>(g_A0 + (size_t)n*FDIM) + tid*4;
        #pragma unroll
        for (int k = 0; k < 4; k++) {
            float4 a = a0[k];
            int f = tid*16 + k*4;   // f%16 cycles the channel
            float c0 = chebB[(f  ) & 15], c1 = chebB[(f+1) & 15];
            float c2 = chebB[(f+2) & 15], c3 = chebB[(f+3) & 15];
            sv[f  ] = fmaxf(a.x + acc[k].x + c0, 0.f);
            sv[f+1] = fmaxf(a.y + acc[k].y + c1, 0.f);
            sv[f+2] = fmaxf(a.z + acc[k].z + c2, 0.f);
            sv[f+3] = fmaxf(a.w + acc[k].w + c3, 0.f);
        }
    }
    __syncthreads();
    for (int idx = tid; idx < FDIM; idx += 256) {
        int bc = idx / TT2, t = idx - bc*TT2;
        int b = bc >> 4, cc = bc & 15;
        g_CH[(((size_t)b*CSV + cc)*NN + n)*TT2 + t] = sv[(b*TT2 + t)*CSV + cc];
    }
}

// ---------------- tail: bn2+relu+residual, bnf+relu ----------------
__global__ void addres_k(const float* __restrict__ y, const float* __restrict__ x,
                         const float* __restrict__ g2, const float* __restrict__ b2) {
    int idx = blockIdx.x*256 + threadIdx.x;
    if (idx >= TOT4) return;
    int t = idx % TT4;
    int r = idx / TT4;
    int n = r % NN;
    int bc = r / NN;
    int c = bc & 63;
    float mu = g_stats[128+c], rs = g_stats[192+c];
    float a = g2[c]*rs;
    float bb = b2[c] - a*mu;
    float h = fmaxf(a*y[idx] + bb, 0.f);
    g_bufS[idx] = h + x[((size_t)bc*NN + n)*TT0 + t];
}
__global__ void final_k(const float* __restrict__ gf, const float* __restrict__ bf,
                        float* __restrict__ out) {
    int idx = blockIdx.x*256 + threadIdx.x;
    if (idx >= TOT4) return;
    int c = (idx / (TT4*NN)) & 63;
    float mu = g_stats[256+c], rs = g_stats[320+c];
    float a = gf[c]*rs;
    float bb = bf[c] - a*mu;
    out[idx] = fmaxf(a*g_bufS[idx] + bb, 0.f);
}

// ---------------- host ----------------
static float* symf(const void* p) { return (float*)p; }

extern "C" void kernel_launch(void* const* d_in, const int* in_sizes, int n_in,
                              void* d_out, int out_size) {
    const float* x    = (const float*)d_in[0];
    const int*   ei   = (const int*)  d_in[1];
    const float* ew   = (const float*)d_in[2];
    const float* t1w1 = (const float*)d_in[3];
    const float* t1b1 = (const float*)d_in[4];
    const float* t1w2 = (const float*)d_in[5];
    const float* t1b2 = (const float*)d_in[6];
    const float* bn1g = (const float*)d_in[7];
    const float* bn1b = (const float*)d_in[8];
    const float* chebW= (const float*)d_in[9];
    const float* chebB= (const float*)d_in[10];
    const float* t2w1 = (const float*)d_in[11];
    const float* t2b1 = (const float*)d_in[12];
    const float* t2w2 = (const float*)d_in[13];
    const float* t2b2 = (const float*)d_in[14];
    const float* bn2g = (const float*)d_in[15];
    const float* bn2b = (const float*)d_in[16];
    const float* bnfg = (const float*)d_in[17];
    const float* bnfb = (const float*)d_in[18];
    float* out = (float*)d_out;

    void *pA, *pB, *pS, *pCH;
    cudaGetSymbolAddress(&pA, g_bufA);
    cudaGetSymbolAddress(&pB, g_bufB);
    cudaGetSymbolAddress(&pS, g_bufS);
    cudaGetSymbolAddress(&pCH, g_CH);
    float* bufA = symf(pA);
    float* bufB = symf(pB);
    float* bufS = symf(pS);
    float* CH   = symf(pCH);

    // graph prep: deg -> rowptr -> CSR fill (norm)
    zero_k<<<(NN+255)/256, 256>>>();
    deg_k<<<EE/256, 256>>>(ei, ew);
    scan_k<<<1, 1024>>>();
    fill_k<<<EE/256, 256>>>(ei, ew);

    // conv1 (relu) : x -> bufA
    conv_k<CCH, TT0, TT1, 32, true><<<dim3(NN, BB, 2), dim3(16, 8)>>>(x, t1w1, t1b1, bufA);
    // conv2 (raw)  : bufA -> bufB, then bn1 stats
    conv_k<CCH, TT1, TT2, 32, false><<<dim3(NN, BB, 2), dim3(16, 8)>>>(bufA, t1w2, t1b2, bufB);
    stats_k<TT2><<<dim3(64, 32), 256>>>(bufB);
    bnfin_k<<<1, 64>>>(0, 1.f/ (float)((size_t)BB*NN*TT2));

    // cheb: projected-first formulation
    chebgemm_k<<<dim3(NN, BB), 120>>>(bufB, bn1g, bn1b, chebW);
    prop1_k<<<NN, 240>>>();
    prop2_k<<<NN, 256>>>(chebB);

    // conv3 (relu) : CH -> bufA ; conv4 (raw) : bufA -> bufB, then bn2 stats
    conv_k<CSV, TT2, TT3, 64, true><<<dim3(NN, BB, 1), dim3(16, 16)>>>(CH, t2w1, t2b1, bufA);
    conv_k<CCH, TT3, TT4, 32, false><<<dim3(NN, BB, 2), dim3(16, 8)>>>(bufA, t2w2, t2b2, bufB);
    stats_k<TT4><<<dim3(64, 32), 256>>>(bufB);
    bnfin_k<<<1, 64>>>(128, 1.f/ (float)((size_t)BB*NN*TT4));

    // s = relu(bn2(conv4)) + residual ; bnf stats ; final
    addres_k<<<(TOT4+255)/256, 256>>>(bufB, x, bn2g, bn2b);
    stats_k<TT4><<<dim3(64, 32), 256>>>(bufS);
    bnfin_k<<<1, 64>>>(256, 1.f/ (float)((size_t)BB*NN*TT4));
    final_k<<<(TOT4+255)/256, 256>>>(bnfg, bnfb, out);
}

// round 6
// speedup vs baseline: 1.3908x; 1.1044x over previous
#include <cuda_runtime.h>
#include <cuda_bf16.h>
#include <math.h>

// ---------------- problem constants ----------------
#define BB 4
#define CCH 64
#define CSV 16
#define NN 2048
#define TT0 64
#define TT1 62
#define TT2 60
#define TT3 58
#define TT4 56
#define EE 32768
#define MM (BB*TT2)   // 240
#define FDIM (MM*CSV) // 3840
#define TOT4 (BB*CCH*NN*TT4)  // 29360128
#define EPSBN 1e-5f
#define TINP 68       // padded smem row (zero-filled tail), mult of 4

typedef unsigned long long u64;

// ---------------- f32x2 packed helpers ----------------
__device__ __forceinline__ u64 pk(float lo, float hi) {
    u64 r; asm("mov.b64 %0, {%1, %2};" : "=l"(r) : "f"(lo), "f"(hi)); return r;
}
__device__ __forceinline__ void unpk(u64 v, float& lo, float& hi) {
    asm("mov.b64 {%0, %1}, %2;" : "=f"(lo), "=f"(hi) : "l"(v));
}
__device__ __forceinline__ void ffma2(u64& d, u64 a, u64 b) {
    asm("fma.rn.f32x2 %0, %1, %2, %0;" : "+l"(d) : "l"(a), "l"(b));
}

// ---------------- scratch (device globals; no runtime alloc) ----------------
__device__ float g_bufA[(size_t)BB*CCH*NN*TT1];   // conv1 out / conv3 out
__device__ float g_bufB[(size_t)BB*CCH*NN*TT2];   // conv2 out / conv4 out
__device__ float g_bufS[(size_t)TOT4];            // relu(bn2)+residual
__device__ float g_A0[(size_t)NN*FDIM];
__device__ float g_Y1[(size_t)NN*FDIM];
__device__ float g_Y2[(size_t)NN*FDIM];
__device__ float g_U [(size_t)NN*FDIM];
__device__ float g_CH[(size_t)BB*CSV*NN*TT2];     // cheb out in (b,c,n,t)
__device__ float g_degw[NN];
__device__ int   g_cnt[NN];
__device__ int   g_off[NN];
__device__ int   g_rowptr[NN+1];
__device__ int   g_ccol[EE];
__device__ float g_cw[EE];
__device__ float g_part[64*32*2];
__device__ float g_stats[6*64];   // [0]mu1 [64]rs1 [128]mu2 [192]rs2 [256]muf [320]rsf

// ---------------- small graph-prep kernels ----------------
__global__ void zero_k() {
    int i = blockIdx.x*blockDim.x + threadIdx.x;
    if (i < NN) { g_degw[i]=0.f; g_cnt[i]=0; g_off[i]=0; }
}
__global__ void deg_k(const int* __restrict__ ei, const float* __restrict__ ew) {
    int e = blockIdx.x*blockDim.x + threadIdx.x;
    if (e < EE) {
        int r = ei[e];
        atomicAdd(&g_degw[r], ew[e]);
        atomicAdd(&g_cnt[r], 1);
    }
}
__global__ void scan_k() {
    __shared__ int a[NN], btmp[NN];
    int tid = threadIdx.x;               // 1024 threads
    a[tid] = g_cnt[tid]; a[tid+1024] = g_cnt[tid+1024];
    __syncthreads();
    int* src = a; int* dst = btmp;
    for (int off = 1; off < NN; off <<= 1) {
        for (int i = tid; i < NN; i += 1024) {
            int v = src[i];
            if (i >= off) v += src[i-off];
            dst[i] = v;
        }
        __syncthreads();
        int* t = src; src = dst; dst = t;
    }
    if (tid == 0) g_rowptr[0] = 0;
    for (int i = tid; i < NN; i += 1024) g_rowptr[i+1] = src[i];
}
__global__ void fill_k(const int* __restrict__ ei, const float* __restrict__ ew) {
    int e = blockIdx.x*blockDim.x + threadIdx.x;
    if (e < EE) {
        int r = ei[e], c = ei[EE+e];
        float dr = g_degw[r], dc = g_degw[c];
        float ir = dr > 0.f ? rsqrtf(dr) : 0.f;
        float ic = dc > 0.f ? rsqrtf(dc) : 0.f;
        float nrm = -ir * ew[e] * ic;
        int pos = g_rowptr[r] + atomicAdd(&g_off[r], 1);
        g_ccol[pos] = c;
        g_cw[pos]   = nrm;
    }
}

// ---------------- temporal conv (1xKS VALID), FFMA2, 4o x 8t tiles ----------
// block (8,16): threadIdx.x = t-group (8 t each), threadIdx.y = o-group (4 o each).
// All 64 out channels per block; one (b,n) per block. Dynamic smem.
template<int CIN, int TIN, int TOUT, bool RELU>
__global__ __launch_bounds__(128) void conv_k(const float* __restrict__ src,
                                              const float* __restrict__ w,
                                              const float* __restrict__ bias,
                                              float* __restrict__ dst) {
    constexpr int OCT = 64;
    constexpr int XSZ = (CIN*TINP > OCT*TOUT) ? CIN*TINP : OCT*TOUT;
    constexpr int NTH = 128;
    extern __shared__ float sm[];
    float* xs = sm;
    float* ws = sm + XSZ;
    const int n = blockIdx.x, b = blockIdx.y;
    const int tid = threadIdx.y*8 + threadIdx.x;

    for (int idx = tid; idx < CIN*TINP; idx += NTH) {
        int i = idx / TINP, t = idx - i*TINP;
        xs[idx] = (t < TIN) ? src[(((size_t)b*CIN + i)*NN + n)*TIN + t] : 0.f;
    }
    for (int idx = tid; idx < CIN*3*OCT; idx += NTH) {
        int k = idx / OCT, ol = idx - k*OCT;
        int i = k/3, kt = k - i*3;
        ws[idx] = w[(ol*CIN + i)*3 + kt];
    }
    __syncthreads();

    const int t0 = threadIdx.x*8;
    const int ob = threadIdx.y*4;
    u64 acc[2][8];
    #pragma unroll
    for (int jp = 0; jp < 2; jp++) {
        #pragma unroll
        for (int u = 0; u < 8; u++) acc[jp][u] = 0ull;
    }

    #pragma unroll 1
    for (int i = 0; i < CIN; i++) {
        const float4 xa = *reinterpret_cast<const float4*>(&xs[i*TINP + t0]);
        const float4 xb = *reinterpret_cast<const float4*>(&xs[i*TINP + t0 + 4]);
        const float2 xc = *reinterpret_cast<const float2*>(&xs[i*TINP + t0 + 8]);
        u64 xd[10];
        xd[0] = pk(xa.x, xa.x); xd[1] = pk(xa.y, xa.y);
        xd[2] = pk(xa.z, xa.z); xd[3] = pk(xa.w, xa.w);
        xd[4] = pk(xb.x, xb.x); xd[5] = pk(xb.y, xb.y);
        xd[6] = pk(xb.z, xb.z); xd[7] = pk(xb.w, xb.w);
        xd[8] = pk(xc.x, xc.x); xd[9] = pk(xc.y, xc.y);
        #pragma unroll
        for (int kt = 0; kt < 3; kt++) {
            ulonglong2 wq = *reinterpret_cast<const ulonglong2*>(&ws[(i*3+kt)*OCT + ob]);
            #pragma unroll
            for (int u = 0; u < 8; u++) {
                ffma2(acc[0][u], wq.x, xd[kt+u]);   // outputs (ob, ob+1)
                ffma2(acc[1][u], wq.y, xd[kt+u]);   // outputs (ob+2, ob+3)
            }
        }
    }
    __syncthreads();  // done reading xs; reuse as output stage

    #pragma unroll
    for (int jp = 0; jp < 2; jp++) {
        float blo = bias[ob + jp*2];
        float bhi = bias[ob + jp*2 + 1];
        int olo = ob + jp*2, ohi = olo + 1;
        #pragma unroll
        for (int u = 0; u < 8; u++) {
            int t = t0 + u;
            if (t < TOUT) {
                float lo, hi; unpk(acc[jp][u], lo, hi);
                float v0 = lo + blo, v1 = hi + bhi;
                if (RELU) { v0 = fmaxf(v0, 0.f); v1 = fmaxf(v1, 0.f); }
                xs[olo*TOUT + t] = v0;
                xs[ohi*TOUT + t] = v1;
            }
        }
    }
    __syncthreads();
    for (int idx = tid; idx < OCT*TOUT; idx += NTH) {
        int o = idx / TOUT, t = idx - o*TOUT;
        dst[(((size_t)b*CCH + o)*NN + n)*TOUT + t] = xs[idx];
    }
}

#define CONV_SMEM(CIN, TOUT) ((((CIN)*TINP > 64*(TOUT)) ? (CIN)*TINP : 64*(TOUT)) + (CIN)*3*64) * sizeof(float)

// ---------------- BN stats (fp32, float4 loads, deterministic) --------------
template<int T>
__global__ void stats_k(const float* __restrict__ src) {
    int c = blockIdx.x, s = blockIdx.y, tid = threadIdx.x;  // 256 thr
    float sum = 0.f, sq = 0.f;
    for (int b = 0; b < BB; b++) {
        const float4* p = reinterpret_cast<const float4*>(src + (((size_t)b*CCH + c)*NN + s*64)*T);
        const int n4 = 64*T/4;
        for (int i = tid; i < n4; i += 256) {
            float4 v = p[i];
            sum += (v.x + v.y) + (v.z + v.w);
            sq  += (v.x*v.x + v.y*v.y) + (v.z*v.z + v.w*v.w);
        }
    }
    __shared__ float sh[512];
    sh[tid] = sum; sh[tid+256] = sq;
    __syncthreads();
    for (int st = 128; st > 0; st >>= 1) {
        if (tid < st) { sh[tid] += sh[tid+st]; sh[tid+256] += sh[tid+256+st]; }
        __syncthreads();
    }
    if (tid == 0) {
        g_part[(c*32+s)*2]   = sh[0];
        g_part[(c*32+s)*2+1] = sh[256];
    }
}
__global__ void bnfin_k(int base, float inv_cnt) {
    int c = threadIdx.x;   // 64 threads
    float s = 0.f, q = 0.f;
    for (int i = 0; i < 32; i++) { s += g_part[(c*32+i)*2]; q += g_part[(c*32+i)*2+1]; }
    float mu = s * inv_cnt;
    float var = q * inv_cnt - mu*mu;
    g_stats[base + c]      = mu;
    g_stats[base + 64 + c] = (float)(1.0 / sqrt((double)var + (double)EPSBN));
}

// ---------------- Cheb channel-mix GEMM (fused bn1+relu input, FFMA2) -------
// out j<16: Tx0(W0-W2) -> g_A0 ; 16..31: Tx0 W1 -> g_Y1 ; 32..47: Tx0 W2 -> g_Y2
__global__ void chebgemm_k(const float* __restrict__ src, const float* __restrict__ g1,
                           const float* __restrict__ b1, const float* __restrict__ chebW) {
    __shared__ float xs[64*TT2];
    __shared__ float ws[64*48];
    __shared__ float stg[TT2*48];
    __shared__ float bna[64], bnb[64];
    const int n = blockIdx.x, b = blockIdx.y, tid = threadIdx.x;  // 120 threads
    if (tid < 64) {
        float mu = g_stats[tid], rs = g_stats[64+tid];
        float a = g1[tid]*rs;
        bna[tid] = a; bnb[tid] = b1[tid] - a*mu;
    }
    __syncthreads();
    for (int idx = tid; idx < 64*TT2; idx += 120) {
        int c = idx / TT2, t = idx - c*TT2;
        float y = src[(((size_t)b*CCH + c)*NN + n)*TT2 + t];
        xs[idx] = fmaxf(bna[c]*y + bnb[c], 0.f);
    }
    for (int idx = tid; idx < 64*48; idx += 120) {
        int c = idx / 48, j = idx - c*48;
        int jj = j & 15;
        float v;
        if (j < 16)      v = chebW[c*16 + jj] - chebW[(128+c)*16 + jj];
        else if (j < 32) v = chebW[(64+c)*16 + jj];
        else             v = chebW[(128+c)*16 + jj];
        ws[idx] = v;
    }
    __syncthreads();
    const int jp = tid % 24, tg = tid / 24;
    const int j0 = jp*2, t0 = tg*12;
    u64 p0[6], p1[6];
    #pragma unroll
    for (int u = 0; u < 6; u++) { p0[u] = 0ull; p1[u] = 0ull; }
    #pragma unroll 2
    for (int c = 0; c < 64; c++) {
        const float4 xa = *reinterpret_cast<const float4*>(&xs[c*TT2 + t0]);
        const float4 xb = *reinterpret_cast<const float4*>(&xs[c*TT2 + t0 + 4]);
        const float4 xc = *reinterpret_cast<const float4*>(&xs[c*TT2 + t0 + 8]);
        u64 xp[6];
        xp[0] = pk(xa.x, xa.y); xp[1] = pk(xa.z, xa.w);
        xp[2] = pk(xb.x, xb.y); xp[3] = pk(xb.z, xb.w);
        xp[4] = pk(xc.x, xc.y); xp[5] = pk(xc.z, xc.w);
        float w0 = ws[c*48 + j0], w1 = ws[c*48 + j0 + 1];
        u64 w0d = pk(w0, w0), w1d = pk(w1, w1);
        #pragma unroll
        for (int u = 0; u < 6; u++) {
            ffma2(p0[u], w0d, xp[u]);
            ffma2(p1[u], w1d, xp[u]);
        }
    }
    #pragma unroll
    for (int u = 0; u < 6; u++) {
        float lo, hi;
        unpk(p0[u], lo, hi);
        stg[(t0+2*u)*48 + j0]       = lo;
        stg[(t0+2*u+1)*48 + j0]     = hi;
        unpk(p1[u], lo, hi);
        stg[(t0+2*u)*48 + j0 + 1]   = lo;
        stg[(t0+2*u+1)*48 + j0 + 1] = hi;
    }
    __syncthreads();
    for (int idx = tid; idx < TT2*48; idx += 120) {
        int t = idx / 48, j = idx - t*48;
        int part = j >> 4, cc = j & 15;
        float* d = (part == 0) ? g_A0 : ((part == 1) ? g_Y1 : g_Y2);
        d[(size_t)n*FDIM + (b*TT2 + t)*CSV + cc] = stg[idx];
    }
}

// ---------------- sparse propagation (CSR gather, float4) -------------------
// 240 threads: thread handles 16 consecutive features (4 float4).
__global__ void prop1_k() {   // U = Y1 + 2*prop(Y2)
    const int n = blockIdx.x, tid = threadIdx.x;  // 240 threads
    const int s = g_rowptr[n], e = g_rowptr[n+1];
    float4 acc[4];
    #pragma unroll
    for (int k = 0; k < 4; k++) acc[k] = make_float4(0.f,0.f,0.f,0.f);
    for (int i = s; i < e; i++) {
        int col = g_ccol[i]; float w = g_cw[i];
        const float4* zp = reinterpret_cast<const float4*>(g_Y2 + (size_t)col*FDIM) + tid*4;
        #pragma unroll
        for (int k = 0; k < 4; k++) {
            float4 v = zp[k];
            acc[k].x = fmaf(w, v.x, acc[k].x);
            acc[k].y = fmaf(w, v.y, acc[k].y);
            acc[k].z = fmaf(w, v.z, acc[k].z);
            acc[k].w = fmaf(w, v.w, acc[k].w);
        }
    }
    const float4* y1 = reinterpret_cast<const float4*>(g_Y1 + (size_t)n*FDIM) + tid*4;
    float4* up = reinterpret_cast<float4*>(g_U + (size_t)n*FDIM) + tid*4;
    #pragma unroll
    for (int k = 0; k < 4; k++) {
        float4 a = y1[k];
        a.x += 2.f*acc[k].x; a.y += 2.f*acc[k].y;
        a.z += 2.f*acc[k].z; a.w += 2.f*acc[k].w;
        up[k] = a;
    }
}
__global__ void prop2_k(const float* __restrict__ chebB) {  // relu(A0+prop(U)+b) -> CH
    const int n = blockIdx.x, tid = threadIdx.x;   // 256 threads (240 accumulate)
    const int s = g_rowptr[n], e = g_rowptr[n+1];
    __shared__ float sv[FDIM];
    if (tid < 240) {
        float4 acc[4];
        #pragma unroll
        for (int k = 0; k < 4; k++) acc[k] = make_float4(0.f,0.f,0.f,0.f);
        for (int i = s; i < e; i++) {
            int col = g_ccol[i]; float w = g_cw[i];
            const float4* zp = reinterpret_cast<const float4*>(g_U + (size_t)col*FDIM) + tid*4;
            #pragma unroll
            for (int k = 0; k < 4; k++) {
                float4 v = zp[k];
                acc[k].x = fmaf(w, v.x, acc[k].x);
                acc[k].y = fmaf(w, v.y, acc[k].y);
                acc[k].z = fmaf(w, v.z, acc[k].z);
                acc[k].w = fmaf(w, v.w, acc[k].w);
            }
        }
        const float4* a0 = reinterpret_cast<const float4*>(g_A0 + (size_t)n*FDIM) + tid*4;
        #pragma unroll
        for (int k = 0; k < 4; k++) {
            float4 a = a0[k];
            int f = tid*16 + k*4;   // f%16 cycles the channel
            float c0 = chebB[(f  ) & 15], c1 = chebB[(f+1) & 15];
            float c2 = chebB[(f+2) & 15], c3 = chebB[(f+3) & 15];
            sv[f  ] = fmaxf(a.x + acc[k].x + c0, 0.f);
            sv[f+1] = fmaxf(a.y + acc[k].y + c1, 0.f);
            sv[f+2] = fmaxf(a.z + acc[k].z + c2, 0.f);
            sv[f+3] = fmaxf(a.w + acc[k].w + c3, 0.f);
        }
    }
    __syncthreads();
    for (int idx = tid; idx < FDIM; idx += 256) {
        int bc = idx / TT2, t = idx - bc*TT2;
        int b = bc >> 4, cc = bc & 15;
        g_CH[(((size_t)b*CSV + cc)*NN + n)*TT2 + t] = sv[(b*TT2 + t)*CSV + cc];
    }
}

// ---------------- tail: bn2+relu+residual, bnf+relu (float4) ----------------
#define NQ4 (TOT4/4)          // 7340032
#define QROW (TT4/4)          // 14
__global__ void addres_k(const float4* __restrict__ y, const float4* __restrict__ x,
                         const float* __restrict__ g2, const float* __restrict__ b2,
                         float4* __restrict__ s) {
    int idx = blockIdx.x*256 + threadIdx.x;
    if (idx >= NQ4) return;
    int q = idx % QROW;
    int r = idx / QROW;
    int n = r % NN;
    int bc = r / NN;
    int c = bc & 63;
    float mu = g_stats[128+c], rs = g_stats[192+c];
    float a = g2[c]*rs;
    float bb = b2[c] - a*mu;
    float4 v = y[idx];
    float4 xr = x[((size_t)bc*NN + n)*(TT0/4) + q];
    float4 o;
    o.x = fmaxf(a*v.x + bb, 0.f) + xr.x;
    o.y = fmaxf(a*v.y + bb, 0.f) + xr.y;
    o.z = fmaxf(a*v.z + bb, 0.f) + xr.z;
    o.w = fmaxf(a*v.w + bb, 0.f) + xr.w;
    s[idx] = o;
}
__global__ void final_k(const float* __restrict__ gf, const float* __restrict__ bf,
                        const float4* __restrict__ s, float4* __restrict__ out) {
    int idx = blockIdx.x*256 + threadIdx.x;
    if (idx >= NQ4) return;
    int c = (idx / (QROW*NN)) & 63;
    float mu = g_stats[256+c], rs = g_stats[320+c];
    float a = gf[c]*rs;
    float bb = bf[c] - a*mu;
    float4 v = s[idx];
    float4 o;
    o.x = fmaxf(a*v.x + bb, 0.f);
    o.y = fmaxf(a*v.y + bb, 0.f);
    o.z = fmaxf(a*v.z + bb, 0.f);
    o.w = fmaxf(a*v.w + bb, 0.f);
    out[idx] = o;
}

// ---------------- host ----------------
static float* symf(const void* p) { return (float*)p; }

extern "C" void kernel_launch(void* const* d_in, const int* in_sizes, int n_in,
                              void* d_out, int out_size) {
    const float* x    = (const float*)d_in[0];
    const int*   ei   = (const int*)  d_in[1];
    const float* ew   = (const float*)d_in[2];
    const float* t1w1 = (const float*)d_in[3];
    const float* t1b1 = (const float*)d_in[4];
    const float* t1w2 = (const float*)d_in[5];
    const float* t1b2 = (const float*)d_in[6];
    const float* bn1g = (const float*)d_in[7];
    const float* bn1b = (const float*)d_in[8];
    const float* chebW= (const float*)d_in[9];
    const float* chebB= (const float*)d_in[10];
    const float* t2w1 = (const float*)d_in[11];
    const float* t2b1 = (const float*)d_in[12];
    const float* t2w2 = (const float*)d_in[13];
    const float* t2b2 = (const float*)d_in[14];
    const float* bn2g = (const float*)d_in[15];
    const float* bn2b = (const float*)d_in[16];
    const float* bnfg = (const float*)d_in[17];
    const float* bnfb = (const float*)d_in[18];
    float* out = (float*)d_out;

    void *pA, *pB, *pS, *pCH;
    cudaGetSymbolAddress(&pA, g_bufA);
    cudaGetSymbolAddress(&pB, g_bufB);
    cudaGetSymbolAddress(&pS, g_bufS);
    cudaGetSymbolAddress(&pCH, g_CH);
    float* bufA = symf(pA);
    float* bufB = symf(pB);
    float* bufS = symf(pS);
    float* CH   = symf(pCH);

    static bool attr_done = false;
    if (!attr_done) {
        cudaFuncSetAttribute(conv_k<CCH, TT0, TT1, true>,  cudaFuncAttributeMaxDynamicSharedMemorySize, CONV_SMEM(CCH, TT1));
        cudaFuncSetAttribute(conv_k<CCH, TT1, TT2, false>, cudaFuncAttributeMaxDynamicSharedMemorySize, CONV_SMEM(CCH, TT2));
        cudaFuncSetAttribute(conv_k<CSV, TT2, TT3, true>,  cudaFuncAttributeMaxDynamicSharedMemorySize, CONV_SMEM(CSV, TT3));
        cudaFuncSetAttribute(conv_k<CCH, TT3, TT4, false>, cudaFuncAttributeMaxDynamicSharedMemorySize, CONV_SMEM(CCH, TT4));
        attr_done = true;
    }

    // graph prep part 1 (deg -> rowptr), then conv1 as the 4th launch (profiled slot)
    zero_k<<<(NN+255)/256, 256>>>();
    deg_k<<<EE/256, 256>>>(ei, ew);
    scan_k<<<1, 1024>>>();

    // conv1 (relu) : x -> bufA   [launch #4 — ncu capture slot]
    conv_k<CCH, TT0, TT1, true><<<dim3(NN, BB), dim3(8, 16), CONV_SMEM(CCH, TT1)>>>(x, t1w1, t1b1, bufA);

    // CSR fill (norm) — needs scan only
    fill_k<<<EE/256, 256>>>(ei, ew);

    // conv2 (raw)  : bufA -> bufB, then bn1 stats
    conv_k<CCH, TT1, TT2, false><<<dim3(NN, BB), dim3(8, 16), CONV_SMEM(CCH, TT2)>>>(bufA, t1w2, t1b2, bufB);
    stats_k<TT2><<<dim3(64, 32), 256>>>(bufB);
    bnfin_k<<<1, 64>>>(0, 1.f/ (float)((size_t)BB*NN*TT2));

    // cheb: projected-first formulation
    chebgemm_k<<<dim3(NN, BB), 120>>>(bufB, bn1g, bn1b, chebW);
    prop1_k<<<NN, 240>>>();
    prop2_k<<<NN, 256>>>(chebB);

    // conv3 (relu) : CH -> bufA ; conv4 (raw) : bufA -> bufB, then bn2 stats
    conv_k<CSV, TT2, TT3, true><<<dim3(NN, BB), dim3(8, 16), CONV_SMEM(CSV, TT3)>>>(CH, t2w1, t2b1, bufA);
    conv_k<CCH, TT3, TT4, false><<<dim3(NN, BB), dim3(8, 16), CONV_SMEM(CCH, TT4)>>>(bufA, t2w2, t2b2, bufB);
    stats_k<TT4><<<dim3(64, 32), 256>>>(bufB);
    bnfin_k<<<1, 64>>>(128, 1.f/ (float)((size_t)BB*NN*TT4));

    // s = relu(bn2(conv4)) + residual ; bnf stats ; final
    addres_k<<<(NQ4+255)/256, 256>>>((const float4*)bufB, (const float4*)x, bn2g, bn2b, (float4*)bufS);
    stats_k<TT4><<<dim3(64, 32), 256>>>(bufS);
    bnfin_k<<<1, 64>>>(256, 1.f/ (float)((size_t)BB*NN*TT4));
    final_k<<<(NQ4+255)/256, 256>>>(bnfg, bnfb, (const float4*)bufS, (float4*)out);
}

// round 7
// speedup vs baseline: 1.5046x; 1.0818x over previous
#include <cuda_runtime.h>
#include <cuda_bf16.h>
#include <math.h>

// ---------------- problem constants ----------------
#define BB 4
#define CCH 64
#define CSV 16
#define NN 2048
#define TT0 64
#define TT1 62
#define TT2 60
#define TT3 58
#define TT4 56
#define EE 32768
#define MM (BB*TT2)   // 240
#define FDIM (MM*CSV) // 3840
#define TOT4 (BB*CCH*NN*TT4)  // 29360128
#define EPSBN 1e-5f
#define TINP 68       // padded smem row (zero-filled tail), mult of 4

typedef unsigned long long u64;

// ---------------- f32x2 packed helpers ----------------
__device__ __forceinline__ u64 pk(float lo, float hi) {
    u64 r; asm("mov.b64 %0, {%1, %2};" : "=l"(r) : "f"(lo), "f"(hi)); return r;
}
__device__ __forceinline__ void unpk(u64 v, float& lo, float& hi) {
    asm("mov.b64 {%0, %1}, %2;" : "=f"(lo), "=f"(hi) : "l"(v));
}
__device__ __forceinline__ void ffma2(u64& d, u64 a, u64 b) {
    asm("fma.rn.f32x2 %0, %1, %2, %0;" : "+l"(d) : "l"(a), "l"(b));
}

// ---------------- scratch (device globals; no runtime alloc) ----------------
__device__ float g_bufA[(size_t)BB*CCH*NN*TT1];   // conv1 out / conv3 out
__device__ float g_bufB[(size_t)BB*CCH*NN*TT2];   // conv2 out / conv4 out
__device__ float g_bufS[(size_t)TOT4];            // relu(bn2)+residual
__device__ float g_A0[(size_t)NN*FDIM];
__device__ float g_Y1[(size_t)NN*FDIM];
__device__ float g_Y2[(size_t)NN*FDIM];
__device__ float g_U [(size_t)NN*FDIM];
__device__ float g_CH[(size_t)BB*CSV*NN*TT2];     // cheb out in (b,c,n,t)
__device__ float g_degw[NN];
__device__ int   g_cnt[NN];
__device__ int   g_off[NN];
__device__ int   g_rowptr[NN+1];
__device__ int   g_ccol[EE];
__device__ float g_cw[EE];
__device__ float g_part[64*32*2];
__device__ float g_stats[6*64];   // [0]mu1 [64]rs1 [128]mu2 [192]rs2 [256]muf [320]rsf

// ---------------- small graph-prep kernels ----------------
__global__ void zero_k() {
    int i = blockIdx.x*blockDim.x + threadIdx.x;
    if (i < NN) { g_degw[i]=0.f; g_cnt[i]=0; g_off[i]=0; }
}
__global__ void deg_k(const int* __restrict__ ei, const float* __restrict__ ew) {
    int e = blockIdx.x*blockDim.x + threadIdx.x;
    if (e < EE) {
        int r = ei[e];
        atomicAdd(&g_degw[r], ew[e]);
        atomicAdd(&g_cnt[r], 1);
    }
}
__global__ void scan_k() {
    __shared__ int a[NN], btmp[NN];
    int tid = threadIdx.x;               // 1024 threads
    a[tid] = g_cnt[tid]; a[tid+1024] = g_cnt[tid+1024];
    __syncthreads();
    int* src = a; int* dst = btmp;
    for (int off = 1; off < NN; off <<= 1) {
        for (int i = tid; i < NN; i += 1024) {
            int v = src[i];
            if (i >= off) v += src[i-off];
            dst[i] = v;
        }
        __syncthreads();
        int* t = src; src = dst; dst = t;
    }
    if (tid == 0) g_rowptr[0] = 0;
    for (int i = tid; i < NN; i += 1024) g_rowptr[i+1] = src[i];
}
__global__ void fill_k(const int* __restrict__ ei, const float* __restrict__ ew) {
    int e = blockIdx.x*blockDim.x + threadIdx.x;
    if (e < EE) {
        int r = ei[e], c = ei[EE+e];
        float dr = g_degw[r], dc = g_degw[c];
        float ir = dr > 0.f ? rsqrtf(dr) : 0.f;
        float ic = dc > 0.f ? rsqrtf(dc) : 0.f;
        float nrm = -ir * ew[e] * ic;
        int pos = g_rowptr[r] + atomicAdd(&g_off[r], 1);
        g_ccol[pos] = c;
        g_cw[pos]   = nrm;
    }
}

// ---------------- temporal conv (1xKS VALID), FFMA2, 4o x 8t tiles ----------
// block (16,8): threadIdx.x = o-group (4 o each), threadIdx.y = t-group (8 t each).
// Warp = 2 t-groups x 16 o-groups: x LDS are pure broadcast (2 addrs, no bank
// conflict); w LDS are 16 distinct contiguous 16B addrs (full wavefronts).
template<int CIN, int TIN, int TOUT, bool RELU>
__global__ __launch_bounds__(128) void conv_k(const float* __restrict__ src,
                                              const float* __restrict__ w,
                                              const float* __restrict__ bias,
                                              float* __restrict__ dst) {
    constexpr int OCT = 64;
    constexpr int XSZ = (CIN*TINP > OCT*TOUT) ? CIN*TINP : OCT*TOUT;
    constexpr int NTH = 128;
    extern __shared__ float sm[];
    float* xs = sm;
    float* ws = sm + XSZ;
    const int n = blockIdx.x, b = blockIdx.y;
    const int tid = threadIdx.y*16 + threadIdx.x;

    for (int idx = tid; idx < CIN*TINP; idx += NTH) {
        int i = idx / TINP, t = idx - i*TINP;
        xs[idx] = (t < TIN) ? src[(((size_t)b*CIN + i)*NN + n)*TIN + t] : 0.f;
    }
    for (int idx = tid; idx < CIN*3*OCT; idx += NTH) {
        int k = idx / OCT, ol = idx - k*OCT;
        int i = k/3, kt = k - i*3;
        ws[idx] = w[(ol*CIN + i)*3 + kt];
    }
    __syncthreads();

    const int t0 = threadIdx.y*8;        // t-group: 8 outputs in t
    const int ob = threadIdx.x*4;        // o-group: 4 outputs in o
    u64 acc[2][8];
    #pragma unroll
    for (int jp = 0; jp < 2; jp++) {
        #pragma unroll
        for (int u = 0; u < 8; u++) acc[jp][u] = 0ull;
    }

    #pragma unroll 2
    for (int i = 0; i < CIN; i++) {
        const float4 xa = *reinterpret_cast<const float4*>(&xs[i*TINP + t0]);
        const float4 xb = *reinterpret_cast<const float4*>(&xs[i*TINP + t0 + 4]);
        const float2 xc = *reinterpret_cast<const float2*>(&xs[i*TINP + t0 + 8]);
        u64 xd[10];
        xd[0] = pk(xa.x, xa.x); xd[1] = pk(xa.y, xa.y);
        xd[2] = pk(xa.z, xa.z); xd[3] = pk(xa.w, xa.w);
        xd[4] = pk(xb.x, xb.x); xd[5] = pk(xb.y, xb.y);
        xd[6] = pk(xb.z, xb.z); xd[7] = pk(xb.w, xb.w);
        xd[8] = pk(xc.x, xc.x); xd[9] = pk(xc.y, xc.y);
        #pragma unroll
        for (int kt = 0; kt < 3; kt++) {
            ulonglong2 wq = *reinterpret_cast<const ulonglong2*>(&ws[(i*3+kt)*OCT + ob]);
            #pragma unroll
            for (int u = 0; u < 8; u++) {
                ffma2(acc[0][u], wq.x, xd[kt+u]);   // outputs (ob, ob+1)
                ffma2(acc[1][u], wq.y, xd[kt+u]);   // outputs (ob+2, ob+3)
            }
        }
    }
    __syncthreads();  // done reading xs; reuse as output stage

    #pragma unroll
    for (int jp = 0; jp < 2; jp++) {
        float blo = bias[ob + jp*2];
        float bhi = bias[ob + jp*2 + 1];
        int olo = ob + jp*2, ohi = olo + 1;
        #pragma unroll
        for (int u = 0; u < 8; u++) {
            int t = t0 + u;
            if (t < TOUT) {
                float lo, hi; unpk(acc[jp][u], lo, hi);
                float v0 = lo + blo, v1 = hi + bhi;
                if (RELU) { v0 = fmaxf(v0, 0.f); v1 = fmaxf(v1, 0.f); }
                xs[olo*TOUT + t] = v0;
                xs[ohi*TOUT + t] = v1;
            }
        }
    }
    __syncthreads();
    for (int idx = tid; idx < OCT*TOUT; idx += NTH) {
        int o = idx / TOUT, t = idx - o*TOUT;
        dst[(((size_t)b*CCH + o)*NN + n)*TOUT + t] = xs[idx];
    }
}

#define CONV_SMEM(CIN, TOUT) ((((CIN)*TINP > 64*(TOUT)) ? (CIN)*TINP : 64*(TOUT)) + (CIN)*3*64) * sizeof(float)

// ---------------- BN stats (fp32, float4 loads, deterministic) --------------
template<int T>
__global__ void stats_k(const float* __restrict__ src) {
    int c = blockIdx.x, s = blockIdx.y, tid = threadIdx.x;  // 256 thr
    float sum = 0.f, sq = 0.f;
    for (int b = 0; b < BB; b++) {
        const float4* p = reinterpret_cast<const float4*>(src + (((size_t)b*CCH + c)*NN + s*64)*T);
        const int n4 = 64*T/4;
        for (int i = tid; i < n4; i += 256) {
            float4 v = p[i];
            sum += (v.x + v.y) + (v.z + v.w);
            sq  += (v.x*v.x + v.y*v.y) + (v.z*v.z + v.w*v.w);
        }
    }
    __shared__ float sh[512];
    sh[tid] = sum; sh[tid+256] = sq;
    __syncthreads();
    for (int st = 128; st > 0; st >>= 1) {
        if (tid < st) { sh[tid] += sh[tid+st]; sh[tid+256] += sh[tid+256+st]; }
        __syncthreads();
    }
    if (tid == 0) {
        g_part[(c*32+s)*2]   = sh[0];
        g_part[(c*32+s)*2+1] = sh[256];
    }
}
__global__ void bnfin_k(int base, float inv_cnt) {
    int c = threadIdx.x;   // 64 threads
    float s = 0.f, q = 0.f;
    for (int i = 0; i < 32; i++) { s += g_part[(c*32+i)*2]; q += g_part[(c*32+i)*2+1]; }
    float mu = s * inv_cnt;
    float var = q * inv_cnt - mu*mu;
    g_stats[base + c]      = mu;
    g_stats[base + 64 + c] = (float)(1.0 / sqrt((double)var + (double)EPSBN));
}

// ---------------- Cheb channel-mix GEMM (fused bn1+relu input, FFMA2) -------
// out j<16: Tx0(W0-W2) -> g_A0 ; 16..31: Tx0 W1 -> g_Y1 ; 32..47: Tx0 W2 -> g_Y2
__global__ void chebgemm_k(const float* __restrict__ src, const float* __restrict__ g1,
                           const float* __restrict__ b1, const float* __restrict__ chebW) {
    __shared__ float xs[64*TT2];
    __shared__ float ws[64*48];
    __shared__ float stg[TT2*48];
    __shared__ float bna[64], bnb[64];
    const int n = blockIdx.x, b = blockIdx.y, tid = threadIdx.x;  // 120 threads
    if (tid < 64) {
        float mu = g_stats[tid], rs = g_stats[64+tid];
        float a = g1[tid]*rs;
        bna[tid] = a; bnb[tid] = b1[tid] - a*mu;
    }
    __syncthreads();
    for (int idx = tid; idx < 64*TT2; idx += 120) {
        int c = idx / TT2, t = idx - c*TT2;
        float y = src[(((size_t)b*CCH + c)*NN + n)*TT2 + t];
        xs[idx] = fmaxf(bna[c]*y + bnb[c], 0.f);
    }
    for (int idx = tid; idx < 64*48; idx += 120) {
        int c = idx / 48, j = idx - c*48;
        int jj = j & 15;
        float v;
        if (j < 16)      v = chebW[c*16 + jj] - chebW[(128+c)*16 + jj];
        else if (j < 32) v = chebW[(64+c)*16 + jj];
        else             v = chebW[(128+c)*16 + jj];
        ws[idx] = v;
    }
    __syncthreads();
    const int jp = tid % 24, tg = tid / 24;
    const int j0 = jp*2, t0 = tg*12;
    u64 p0[6], p1[6];
    #pragma unroll
    for (int u = 0; u < 6; u++) { p0[u] = 0ull; p1[u] = 0ull; }
    #pragma unroll 2
    for (int c = 0; c < 64; c++) {
        const float4 xa = *reinterpret_cast<const float4*>(&xs[c*TT2 + t0]);
        const float4 xb = *reinterpret_cast<const float4*>(&xs[c*TT2 + t0 + 4]);
        const float4 xc = *reinterpret_cast<const float4*>(&xs[c*TT2 + t0 + 8]);
        u64 xp[6];
        xp[0] = pk(xa.x, xa.y); xp[1] = pk(xa.z, xa.w);
        xp[2] = pk(xb.x, xb.y); xp[3] = pk(xb.z, xb.w);
        xp[4] = pk(xc.x, xc.y); xp[5] = pk(xc.z, xc.w);
        float w0 = ws[c*48 + j0], w1 = ws[c*48 + j0 + 1];
        u64 w0d = pk(w0, w0), w1d = pk(w1, w1);
        #pragma unroll
        for (int u = 0; u < 6; u++) {
            ffma2(p0[u], w0d, xp[u]);
            ffma2(p1[u], w1d, xp[u]);
        }
    }
    #pragma unroll
    for (int u = 0; u < 6; u++) {
        float lo, hi;
        unpk(p0[u], lo, hi);
        stg[(t0+2*u)*48 + j0]       = lo;
        stg[(t0+2*u+1)*48 + j0]     = hi;
        unpk(p1[u], lo, hi);
        stg[(t0+2*u)*48 + j0 + 1]   = lo;
        stg[(t0+2*u+1)*48 + j0 + 1] = hi;
    }
    __syncthreads();
    for (int idx = tid; idx < TT2*48; idx += 120) {
        int t = idx / 48, j = idx - t*48;
        int part = j >> 4, cc = j & 15;
        float* d = (part == 0) ? g_A0 : ((part == 1) ? g_Y1 : g_Y2);
        d[(size_t)n*FDIM + (b*TT2 + t)*CSV + cc] = stg[idx];
    }
}

// ---------------- sparse propagation (CSR gather, float4) -------------------
// 240 threads: thread handles 16 consecutive features (4 float4).
__global__ void prop1_k() {   // U = Y1 + 2*prop(Y2)
    const int n = blockIdx.x, tid = threadIdx.x;  // 240 threads
    const int s = g_rowptr[n], e = g_rowptr[n+1];
    float4 acc[4];
    #pragma unroll
    for (int k = 0; k < 4; k++) acc[k] = make_float4(0.f,0.f,0.f,0.f);
    for (int i = s; i < e; i++) {
        int col = g_ccol[i]; float w = g_cw[i];
        const float4* zp = reinterpret_cast<const float4*>(g_Y2 + (size_t)col*FDIM) + tid*4;
        #pragma unroll
        for (int k = 0; k < 4; k++) {
            float4 v = zp[k];
            acc[k].x = fmaf(w, v.x, acc[k].x);
            acc[k].y = fmaf(w, v.y, acc[k].y);
            acc[k].z = fmaf(w, v.z, acc[k].z);
            acc[k].w = fmaf(w, v.w, acc[k].w);
        }
    }
    const float4* y1 = reinterpret_cast<const float4*>(g_Y1 + (size_t)n*FDIM) + tid*4;
    float4* up = reinterpret_cast<float4*>(g_U + (size_t)n*FDIM) + tid*4;
    #pragma unroll
    for (int k = 0; k < 4; k++) {
        float4 a = y1[k];
        a.x += 2.f*acc[k].x; a.y += 2.f*acc[k].y;
        a.z += 2.f*acc[k].z; a.w += 2.f*acc[k].w;
        up[k] = a;
    }
}
__global__ void prop2_k(const float* __restrict__ chebB) {  // relu(A0+prop(U)+b) -> CH
    const int n = blockIdx.x, tid = threadIdx.x;   // 256 threads (240 accumulate)
    const int s = g_rowptr[n], e = g_rowptr[n+1];
    __shared__ float sv[FDIM];
    if (tid < 240) {
        float4 acc[4];
        #pragma unroll
        for (int k = 0; k < 4; k++) acc[k] = make_float4(0.f,0.f,0.f,0.f);
        for (int i = s; i < e; i++) {
            int col = g_ccol[i]; float w = g_cw[i];
            const float4* zp = reinterpret_cast<const float4*>(g_U + (size_t)col*FDIM) + tid*4;
            #pragma unroll
            for (int k = 0; k < 4; k++) {
                float4 v = zp[k];
                acc[k].x = fmaf(w, v.x, acc[k].x);
                acc[k].y = fmaf(w, v.y, acc[k].y);
                acc[k].z = fmaf(w, v.z, acc[k].z);
                acc[k].w = fmaf(w, v.w, acc[k].w);
            }
        }
        const float4* a0 = reinterpret_cast<const float4*>(g_A0 + (size_t)n*FDIM) + tid*4;
        #pragma unroll
        for (int k = 0; k < 4; k++) {
            float4 a = a0[k];
            int f = tid*16 + k*4;   // f%16 cycles the channel
            float c0 = chebB[(f  ) & 15], c1 = chebB[(f+1) & 15];
            float c2 = chebB[(f+2) & 15], c3 = chebB[(f+3) & 15];
            sv[f  ] = fmaxf(a.x + acc[k].x + c0, 0.f);
            sv[f+1] = fmaxf(a.y + acc[k].y + c1, 0.f);
            sv[f+2] = fmaxf(a.z + acc[k].z + c2, 0.f);
            sv[f+3] = fmaxf(a.w + acc[k].w + c3, 0.f);
        }
    }
    __syncthreads();
    for (int idx = tid; idx < FDIM; idx += 256) {
        int bc = idx / TT2, t = idx - bc*TT2;
        int b = bc >> 4, cc = bc & 15;
        g_CH[(((size_t)b*CSV + cc)*NN + n)*TT2 + t] = sv[(b*TT2 + t)*CSV + cc];
    }
}

// ---------------- tail: bn2+relu+residual, bnf+relu (float4) ----------------
#define NQ4 (TOT4/4)          // 7340032
#define QROW (TT4/4)          // 14
__global__ void addres_k(const float4* __restrict__ y, const float4* __restrict__ x,
                         const float* __restrict__ g2, const float* __restrict__ b2,
                         float4* __restrict__ s) {
    int idx = blockIdx.x*256 + threadIdx.x;
    if (idx >= NQ4) return;
    int q = idx % QROW;
    int r = idx / QROW;
    int n = r % NN;
    int bc = r / NN;
    int c = bc & 63;
    float mu = g_stats[128+c], rs = g_stats[192+c];
    float a = g2[c]*rs;
    float bb = b2[c] - a*mu;
    float4 v = y[idx];
    float4 xr = x[((size_t)bc*NN + n)*(TT0/4) + q];
    float4 o;
    o.x = fmaxf(a*v.x + bb, 0.f) + xr.x;
    o.y = fmaxf(a*v.y + bb, 0.f) + xr.y;
    o.z = fmaxf(a*v.z + bb, 0.f) + xr.z;
    o.w = fmaxf(a*v.w + bb, 0.f) + xr.w;
    s[idx] = o;
}
__global__ void final_k(const float* __restrict__ gf, const float* __restrict__ bf,
                        const float4* __restrict__ s, float4* __restrict__ out) {
    int idx = blockIdx.x*256 + threadIdx.x;
    if (idx >= NQ4) return;
    int c = (idx / (QROW*NN)) & 63;
    float mu = g_stats[256+c], rs = g_stats[320+c];
    float a = gf[c]*rs;
    float bb = bf[c] - a*mu;
    float4 v = s[idx];
    float4 o;
    o.x = fmaxf(a*v.x + bb, 0.f);
    o.y = fmaxf(a*v.y + bb, 0.f);
    o.z = fmaxf(a*v.z + bb, 0.f);
    o.w = fmaxf(a*v.w + bb, 0.f);
    out[idx] = o;
}

// ---------------- host ----------------
static float* symf(const void* p) { return (float*)p; }

extern "C" void kernel_launch(void* const* d_in, const int* in_sizes, int n_in,
                              void* d_out, int out_size) {
    const float* x    = (const float*)d_in[0];
    const int*   ei   = (const int*)  d_in[1];
    const float* ew   = (const float*)d_in[2];
    const float* t1w1 = (const float*)d_in[3];
    const float* t1b1 = (const float*)d_in[4];
    const float* t1w2 = (const float*)d_in[5];
    const float* t1b2 = (const float*)d_in[6];
    const float* bn1g = (const float*)d_in[7];
    const float* bn1b = (const float*)d_in[8];
    const float* chebW= (const float*)d_in[9];
    const float* chebB= (const float*)d_in[10];
    const float* t2w1 = (const float*)d_in[11];
    const float* t2b1 = (const float*)d_in[12];
    const float* t2w2 = (const float*)d_in[13];
    const float* t2b2 = (const float*)d_in[14];
    const float* bn2g = (const float*)d_in[15];
    const float* bn2b = (const float*)d_in[16];
    const float* bnfg = (const float*)d_in[17];
    const float* bnfb = (const float*)d_in[18];
    float* out = (float*)d_out;

    void *pA, *pB, *pS, *pCH;
    cudaGetSymbolAddress(&pA, g_bufA);
    cudaGetSymbolAddress(&pB, g_bufB);
    cudaGetSymbolAddress(&pS, g_bufS);
    cudaGetSymbolAddress(&pCH, g_CH);
    float* bufA = symf(pA);
    float* bufB = symf(pB);
    float* bufS = symf(pS);
    float* CH   = symf(pCH);

    static bool attr_done = false;
    if (!attr_done) {
        cudaFuncSetAttribute(conv_k<CCH, TT0, TT1, true>,  cudaFuncAttributeMaxDynamicSharedMemorySize, CONV_SMEM(CCH, TT1));
        cudaFuncSetAttribute(conv_k<CCH, TT1, TT2, false>, cudaFuncAttributeMaxDynamicSharedMemorySize, CONV_SMEM(CCH, TT2));
        cudaFuncSetAttribute(conv_k<CSV, TT2, TT3, true>,  cudaFuncAttributeMaxDynamicSharedMemorySize, CONV_SMEM(CSV, TT3));
        cudaFuncSetAttribute(conv_k<CCH, TT3, TT4, false>, cudaFuncAttributeMaxDynamicSharedMemorySize, CONV_SMEM(CCH, TT4));
        attr_done = true;
    }

    // graph prep part 1 (deg -> rowptr), then conv1 as the 4th launch (profiled slot)
    zero_k<<<(NN+255)/256, 256>>>();
    deg_k<<<EE/256, 256>>>(ei, ew);
    scan_k<<<1, 1024>>>();

    // conv1 (relu) : x -> bufA   [launch #4 — ncu capture slot]
    conv_k<CCH, TT0, TT1, true><<<dim3(NN, BB), dim3(16, 8), CONV_SMEM(CCH, TT1)>>>(x, t1w1, t1b1, bufA);

    // CSR fill (norm) — needs scan only
    fill_k<<<EE/256, 256>>>(ei, ew);

    // conv2 (raw)  : bufA -> bufB, then bn1 stats
    conv_k<CCH, TT1, TT2, false><<<dim3(NN, BB), dim3(16, 8), CONV_SMEM(CCH, TT2)>>>(bufA, t1w2, t1b2, bufB);
    stats_k<TT2><<<dim3(64, 32), 256>>>(bufB);
    bnfin_k<<<1, 64>>>(0, 1.f/ (float)((size_t)BB*NN*TT2));

    // cheb: projected-first formulation
    chebgemm_k<<<dim3(NN, BB), 120>>>(bufB, bn1g, bn1b, chebW);
    prop1_k<<<NN, 240>>>();
    prop2_k<<<NN, 256>>>(chebB);

    // conv3 (relu) : CH -> bufA ; conv4 (raw) : bufA -> bufB, then bn2 stats
    conv_k<CSV, TT2, TT3, true><<<dim3(NN, BB), dim3(16, 8), CONV_SMEM(CSV, TT3)>>>(CH, t2w1, t2b1, bufA);
    conv_k<CCH, TT3, TT4, false><<<dim3(NN, BB), dim3(16, 8), CONV_SMEM(CCH, TT4)>>>(bufA, t2w2, t2b2, bufB);
    stats_k<TT4><<<dim3(64, 32), 256>>>(bufB);
    bnfin_k<<<1, 64>>>(128, 1.f/ (float)((size_t)BB*NN*TT4));

    // s = relu(bn2(conv4)) + residual ; bnf stats ; final
    addres_k<<<(NQ4+255)/256, 256>>>((const float4*)bufB, (const float4*)x, bn2g, bn2b, (float4*)bufS);
    stats_k<TT4><<<dim3(64, 32), 256>>>(bufS);
    bnfin_k<<<1, 64>>>(256, 1.f/ (float)((size_t)BB*NN*TT4));
    final_k<<<(NQ4+255)/256, 256>>>(bnfg, bnfb, (const float4*)bufS, (float4*)out);
}